// round 1
// baseline (speedup 1.0000x reference)
#include <cuda_runtime.h>
#include <math.h>

// Problem constants
#define LQ    2048          // sequence length L
#define BQ    8             // batch
#define DQ    1024          // hidden
#define NDIMQ 16            // modes
#define KDQ   (2*DQ)        // 2048 coefficient rows (k1 rows then k2 rows)
#define CQ    16            // chunks
#define CLQ   (LQ/CQ)       // 128 chunk length
#define BD    (BQ*DQ)       // 8192 sequences

// Device scratch (no dynamic allocation allowed)
__device__ float g_q [KDQ*NDIMQ];
__device__ float g_c [KDQ*NDIMQ];
__device__ float g_qp[KDQ*NDIMQ];
__device__ float g_local[2][BD*CQ*NDIMQ];
__device__ float g_carry[2][BD*CQ*NDIMQ];

__global__ __launch_bounds__(256) void coeff_kernel(
    const float* __restrict__ damp, const float* __restrict__ decay,
    const float* __restrict__ ema,  const float* __restrict__ proj)
{
    int i = blockIdx.x * blockDim.x + threadIdx.x;
    if (i >= KDQ*NDIMQ) return;
    float p  = 1.f / (1.f + expf(-damp[i]));
    float sd = 1.f / (1.f + expf(-decay[i]));
    float q  = 1.f - p * sd;
    g_q[i]  = q;
    g_c[i]  = p * ema[i] * proj[i] * 0.25f;   // scale = 1/sqrt(16)
    g_qp[i] = powf(q, (float)CLQ);
}

// Phase 1: per-(dir, chunk, b, d) chunk-local final state (starting from 0)
__global__ __launch_bounds__(256) void local_kernel(
    const float* __restrict__ x, const int* __restrict__ mask)
{
    int idx = blockIdx.x * blockDim.x + threadIdx.x;   // 2*CQ*BQ*DQ threads
    int d     = idx & (DQ-1);
    int b     = (idx >> 10) & (BQ-1);
    int chunk = (idx >> 13) & (CQ-1);
    int dir   = idx >> 17;
    int row   = d + dir*DQ;
    int s     = b*DQ + d;

    float q[NDIMQ], h[NDIMQ];
#pragma unroll
    for (int n = 0; n < NDIMQ; n++) { q[n] = g_q[row*NDIMQ + n]; h[n] = 0.f; }

    if (dir == 0) {
        int t0 = chunk * CLQ;
        for (int j = 0; j < CLQ; j++) {
            int t = t0 + j;
            float xv = x[t*BD + s] * (float)mask[b*LQ + t];
#pragma unroll
            for (int n = 0; n < NDIMQ; n++) h[n] = fmaf(q[n], h[n], xv);
        }
    } else {
        int t0 = chunk * CLQ + CLQ - 1;
        for (int j = 0; j < CLQ; j++) {
            int t = t0 - j;
            float xv = x[t*BD + s] * (float)mask[b*LQ + t];
#pragma unroll
            for (int n = 0; n < NDIMQ; n++) h[n] = fmaf(q[n], h[n], xv);
        }
    }
    float* dst = &g_local[dir][(s*CQ + chunk)*NDIMQ];
#pragma unroll
    for (int n = 0; n < NDIMQ; n++) dst[n] = h[n];
}

// Phase 2: inter-chunk scan -> carry (state entering each chunk)
__global__ __launch_bounds__(256) void carry_kernel()
{
    int idx = blockIdx.x * blockDim.x + threadIdx.x;   // 2*BQ*DQ*NDIMQ threads
    int n   = idx & (NDIMQ-1);
    int d   = (idx >> 4) & (DQ-1);
    int b   = (idx >> 14) & (BQ-1);
    int dir = idx >> 17;
    int s   = b*DQ + d;
    int row = d + dir*DQ;

    float qp = g_qp[row*NDIMQ + n];
    const float* loc = &g_local[dir][s*CQ*NDIMQ + n];
    float*       car = &g_carry[dir][s*CQ*NDIMQ + n];
    float acc = 0.f;
    if (dir == 0) {
        for (int c = 0; c < CQ; c++) {
            car[c*NDIMQ] = acc;
            acc = fmaf(qp, acc, loc[c*NDIMQ]);
        }
    } else {
        for (int c = CQ-1; c >= 0; c--) {
            car[c*NDIMQ] = acc;
            acc = fmaf(qp, acc, loc[c*NDIMQ]);
        }
    }
}

// Phase 3a: forward scan with carry; out = s1 + residual
__global__ __launch_bounds__(256) void fwd_kernel(
    const float* __restrict__ x, const int* __restrict__ mask,
    const float* __restrict__ rw, float* __restrict__ out)
{
    int idx = blockIdx.x * blockDim.x + threadIdx.x;   // BQ*DQ*CQ threads
    int d     = idx & (DQ-1);
    int b     = (idx >> 10) & (BQ-1);
    int chunk = idx >> 13;
    int s     = b*DQ + d;

    float q[NDIMQ], c[NDIMQ], h[NDIMQ];
    const float* car = &g_carry[0][(s*CQ + chunk)*NDIMQ];
#pragma unroll
    for (int n = 0; n < NDIMQ; n++) {
        q[n] = g_q[d*NDIMQ + n];
        c[n] = g_c[d*NDIMQ + n];
        h[n] = car[n];
    }
    float w = rw[d];
    int t0 = chunk * CLQ;
    for (int j = 0; j < CLQ; j++) {
        int t = t0 + j;
        float xr = x[t*BD + s];
        float xv = xr * (float)mask[b*LQ + t];
#pragma unroll
        for (int n = 0; n < NDIMQ; n++) h[n] = fmaf(q[n], h[n], xv);
        float a0 = 0.f, a1 = 0.f, a2 = 0.f, a3 = 0.f;
#pragma unroll
        for (int n = 0; n < NDIMQ; n += 4) {
            a0 = fmaf(c[n+0], h[n+0], a0);
            a1 = fmaf(c[n+1], h[n+1], a1);
            a2 = fmaf(c[n+2], h[n+2], a2);
            a3 = fmaf(c[n+3], h[n+3], a3);
        }
        out[t*BD + s] = (a0+a1) + (a2+a3) + xr*w;
    }
}

// Phase 3b: backward scan with carry; out = silu(out + s2)
__global__ __launch_bounds__(256) void bwd_kernel(
    const float* __restrict__ x, const int* __restrict__ mask,
    float* __restrict__ out)
{
    int idx = blockIdx.x * blockDim.x + threadIdx.x;   // BQ*DQ*CQ threads
    int d     = idx & (DQ-1);
    int b     = (idx >> 10) & (BQ-1);
    int chunk = idx >> 13;
    int s     = b*DQ + d;
    int row   = d + DQ;

    float q[NDIMQ], c[NDIMQ], g[NDIMQ];
    const float* car = &g_carry[1][(s*CQ + chunk)*NDIMQ];
#pragma unroll
    for (int n = 0; n < NDIMQ; n++) {
        q[n] = g_q[row*NDIMQ + n];
        c[n] = g_c[row*NDIMQ + n];
        g[n] = car[n];
    }
    int t0 = chunk * CLQ + CLQ - 1;
    for (int j = 0; j < CLQ; j++) {
        int t = t0 - j;
        float xr = x[t*BD + s];
        float xv = xr * (float)mask[b*LQ + t];
#pragma unroll
        for (int n = 0; n < NDIMQ; n++) g[n] = fmaf(q[n], g[n], xv);
        float a0 = 0.f, a1 = 0.f, a2 = 0.f, a3 = 0.f;
#pragma unroll
        for (int n = 0; n < NDIMQ; n += 4) {
            a0 = fmaf(c[n+0], g[n+0], a0);
            a1 = fmaf(c[n+1], g[n+1], a1);
            a2 = fmaf(c[n+2], g[n+2], a2);
            a3 = fmaf(c[n+3], g[n+3], a3);
        }
        float v = out[t*BD + s] + (a0+a1) + (a2+a3);
        out[t*BD + s] = v * (1.f / (1.f + __expf(-v)));   // silu
    }
}

extern "C" void kernel_launch(void* const* d_in, const int* in_sizes, int n_in,
                              void* d_out, int out_size)
{
    const float* x     = (const float*)d_in[0];   // (L, B, D)
    const float* damp  = (const float*)d_in[1];   // (2D, 16, 1)
    const float* decay = (const float*)d_in[2];
    const float* ema   = (const float*)d_in[3];
    const float* proj  = (const float*)d_in[4];   // (2D, 16)
    const float* rw    = (const float*)d_in[5];   // (D,)
    const int*   mask  = (const int*)  d_in[6];   // (B, L)
    float* out = (float*)d_out;

    coeff_kernel<<<(KDQ*NDIMQ + 255)/256, 256>>>(damp, decay, ema, proj);
    local_kernel<<<(2*CQ*BQ*DQ)/256, 256>>>(x, mask);
    carry_kernel<<<(2*BQ*DQ*NDIMQ)/256, 256>>>();
    fwd_kernel<<<(BQ*DQ*CQ)/256, 256>>>(x, mask, rw, out);
    bwd_kernel<<<(BQ*DQ*CQ)/256, 256>>>(x, mask, out);
}